// round 1
// baseline (speedup 1.0000x reference)
#include <cuda_runtime.h>
#include <cuda_bf16.h>
#include <math.h>

// Problem constants (fixed by setup_inputs)
#define BB   2
#define LL   2048
#define DD   2048
#define EE   96      // dt_rank + 2*d_state
#define RR   64      // dt_rank
#define NS   16      // d_state
#define MM   (BB*LL) // 4096 rows

// Scratch (device globals: no cudaMalloc allowed)
__device__ float g_xdbl[MM * EE];          // (B*L, 96): [0:64)=dlt, [64:80)=B, [80:96)=C
__device__ float g_delta[MM * DD];         // (B*L, 2048) softplus'd delta

__device__ __forceinline__ float ex2f(float v) {
    float r; asm("ex2.approx.f32 %0, %1;" : "=f"(r) : "f"(v)); return r;
}

__device__ __forceinline__ float softplus_f(float z) {
    // accurate enough; guarded against overflow
    if (z > 15.f) return z;
    return log1pf(__expf(z));
}

// ---------------------------------------------------------------------------
// Kernel 1: x_dbl = x @ W_xproj^T   (M=4096, K=2048, N=96)
// BM=32, BN=96, BK=32; 128 blocks x 128 threads; thread tile 4x6.
// ---------------------------------------------------------------------------
__global__ void __launch_bounds__(128) xproj_kernel(const float* __restrict__ x,
                                                    const float* __restrict__ Wx) {
    __shared__ float xs[32][33];
    __shared__ float ws[96][33];
    const int m0  = blockIdx.x * 32;
    const int tid = threadIdx.x;
    const int tm  = tid >> 4;   // 0..7
    const int tn  = tid & 15;   // 0..15

    float acc[4][6];
#pragma unroll
    for (int i = 0; i < 4; i++)
#pragma unroll
        for (int j = 0; j < 6; j++) acc[i][j] = 0.f;

    for (int kt = 0; kt < 2048; kt += 32) {
#pragma unroll
        for (int e = 0; e < 8; e++) {
            int idx = e * 128 + tid;
            int r = idx >> 5, c = idx & 31;
            xs[r][c] = x[(m0 + r) * 2048 + kt + c];
        }
#pragma unroll
        for (int e = 0; e < 24; e++) {
            int idx = e * 128 + tid;
            int r = idx >> 5, c = idx & 31;
            ws[r][c] = Wx[r * 2048 + kt + c];
        }
        __syncthreads();
#pragma unroll
        for (int kk = 0; kk < 32; kk++) {
            float ar[4], br[6];
#pragma unroll
            for (int i = 0; i < 4; i++) ar[i] = xs[tm * 4 + i][kk];
#pragma unroll
            for (int j = 0; j < 6; j++) br[j] = ws[tn * 6 + j][kk];
#pragma unroll
            for (int i = 0; i < 4; i++)
#pragma unroll
                for (int j = 0; j < 6; j++)
                    acc[i][j] = fmaf(ar[i], br[j], acc[i][j]);
        }
        __syncthreads();
    }
#pragma unroll
    for (int i = 0; i < 4; i++)
#pragma unroll
        for (int j = 0; j < 6; j++)
            g_xdbl[(m0 + tm * 4 + i) * EE + tn * 6 + j] = acc[i][j];
}

// ---------------------------------------------------------------------------
// Kernel 2: delta = softplus(dlt @ W_dt^T + b_dt)  (M=4096, N=2048, K=64)
// BM=64, BN=64; grid (32, 64) x 256 threads; thread tile 4x4.
// ---------------------------------------------------------------------------
__global__ void __launch_bounds__(256) delta_kernel(const float* __restrict__ Wdt,
                                                    const float* __restrict__ bdt) {
    __shared__ float as_[64][65];
    __shared__ float bs_[64][65];
    const int n0  = blockIdx.x * 64;
    const int m0  = blockIdx.y * 64;
    const int tid = threadIdx.x;

#pragma unroll
    for (int e = 0; e < 16; e++) {
        int idx = e * 256 + tid;
        int r = idx >> 6, c = idx & 63;
        as_[r][c] = g_xdbl[(m0 + r) * EE + c];       // dlt part (cols 0..63)
        bs_[r][c] = Wdt[(n0 + r) * 64 + c];
    }
    __syncthreads();

    const int tm = tid >> 4, tn = tid & 15;
    float acc[4][4] = {};
#pragma unroll 8
    for (int k = 0; k < 64; k++) {
        float ar[4], br[4];
#pragma unroll
        for (int i = 0; i < 4; i++) ar[i] = as_[tm * 4 + i][k];
#pragma unroll
        for (int j = 0; j < 4; j++) br[j] = bs_[tn * 4 + j][k];
#pragma unroll
        for (int i = 0; i < 4; i++)
#pragma unroll
            for (int j = 0; j < 4; j++)
                acc[i][j] = fmaf(ar[i], br[j], acc[i][j]);
    }

    const int n = n0 + tn * 4;
    float b0 = bdt[n + 0], b1 = bdt[n + 1], b2 = bdt[n + 2], b3 = bdt[n + 3];
#pragma unroll
    for (int i = 0; i < 4; i++) {
        int m = m0 + tm * 4 + i;
        float4 o;
        o.x = softplus_f(acc[i][0] + b0);
        o.y = softplus_f(acc[i][1] + b1);
        o.z = softplus_f(acc[i][2] + b2);
        o.w = softplus_f(acc[i][3] + b3);
        *(float4*)&g_delta[m * DD + n] = o;
    }
}

// ---------------------------------------------------------------------------
// Kernel 3: selective scan.
// Lane layout: lane = c*4 + s ; c = channel-in-warp (0..7), s = state group
// (states 4s..4s+3). 8 channels/warp, 32 channels/block, 128 blocks x 128 thr.
// ---------------------------------------------------------------------------
__global__ void __launch_bounds__(128) scan_kernel(const float* __restrict__ x,
                                                   const float* __restrict__ A_log,
                                                   const float* __restrict__ Dp_,
                                                   float* __restrict__ out) {
    const int tid  = threadIdx.x;
    const int warp = tid >> 5;
    const int lane = tid & 31;
    const int c    = lane >> 2;
    const int s    = lane & 3;
    const int b    = blockIdx.x >> 6;
    const int d    = ((blockIdx.x & 63) << 5) + warp * 8 + c;

    const float LOG2E = 1.4426950408889634f;
    float aa[4];
#pragma unroll
    for (int j = 0; j < 4; j++)
        aa[j] = -__expf(A_log[(d << 4) + (s << 2) + j]) * LOG2E;
    const float Dv = Dp_[d];

    float h0 = 0.f, h1 = 0.f, h2 = 0.f, h3 = 0.f;

    const int base = b * (LL * DD) + d;
    const float* pd = g_delta + base;
    const float* px = x + base;
    const float* pb = g_xdbl + (b * LL) * EE + 64 + s * 4;   // B; C at +16
    float* po = out + base;

    // prefetch t=0
    float  dv = pd[0];
    float  uv = px[0];
    float4 Bv = *(const float4*)pb;
    float4 Cv = *(const float4*)(pb + 16);

#pragma unroll 4
    for (int t = 0; t < LL; t++) {
        float  dvc = dv, uvc = uv;
        float4 Bc = Bv, Cc = Cv;
        if (t < LL - 1) {
            pd += DD; px += DD; pb += EE;
            dv = pd[0];
            uv = px[0];
            Bv = *(const float4*)pb;
            Cv = *(const float4*)(pb + 16);
        }

        float du = dvc * uvc;
        h0 = fmaf(ex2f(dvc * aa[0]), h0, du * Bc.x);
        h1 = fmaf(ex2f(dvc * aa[1]), h1, du * Bc.y);
        h2 = fmaf(ex2f(dvc * aa[2]), h2, du * Bc.z);
        h3 = fmaf(ex2f(dvc * aa[3]), h3, du * Bc.w);

        float y = h0 * Cc.x;
        y = fmaf(h1, Cc.y, y);
        y = fmaf(h2, Cc.z, y);
        y = fmaf(h3, Cc.w, y);
        y += __shfl_xor_sync(0xffffffffu, y, 1);
        y += __shfl_xor_sync(0xffffffffu, y, 2);

        if (s == 0) po[0] = fmaf(uvc, Dv, y);
        po += DD;
    }
}

// ---------------------------------------------------------------------------
extern "C" void kernel_launch(void* const* d_in, const int* in_sizes, int n_in,
                              void* d_out, int out_size) {
    const float* x     = (const float*)d_in[0];
    const float* Wx    = (const float*)d_in[1];
    const float* Wdt   = (const float*)d_in[2];
    const float* bdt   = (const float*)d_in[3];
    const float* A_log = (const float*)d_in[4];
    const float* Dp    = (const float*)d_in[5];
    float* out = (float*)d_out;

    xproj_kernel<<<MM / 32, 128>>>(x, Wx);
    delta_kernel<<<dim3(DD / 64, MM / 64), 256>>>(Wdt, bdt);
    scan_kernel<<<128, 128>>>(x, A_log, Dp, out);
}

// round 2
// speedup vs baseline: 2.6343x; 2.6343x over previous
#include <cuda_runtime.h>
#include <cuda_bf16.h>
#include <math.h>

#define BB   2
#define LL   2048
#define DD   2048
#define EE   96
#define RR   64
#define NS   16
#define MM   (BB*LL)     // 4096
#define NCH  (BB*DD)     // 4096 channels
#define CHUNKS 8
#define TT   (LL/CHUNKS) // 256
#define KSPLIT 4

// Scratch (device globals; no cudaMalloc allowed)
__device__ float g_xdbl_part[KSPLIT * MM * EE];
__device__ float g_xdbl[MM * EE];            // [0:64)=dlt, [64:80)=B, [80:96)=C
__device__ float g_delta[MM * DD];
__device__ float g_P[(CHUNKS-1) * NCH * NS];
__device__ float g_q[(CHUNKS-1) * NCH * NS];
__device__ float g_hin[CHUNKS * NCH * NS];

__device__ __forceinline__ float ex2f(float v) {
    float r; asm("ex2.approx.f32 %0, %1;" : "=f"(r) : "f"(v)); return r;
}
__device__ __forceinline__ float softplus_f(float z) {
    if (z > 15.f) return z;
    return log1pf(__expf(z));
}

// ---------------------------------------------------------------------------
// Kernel 1: x_dbl = x @ W_xproj^T   (M=4096, K=2048, N=96), split-K=4
// BM=64, BN=96, BK=16; 256 threads; thread tile 4x6. grid (64, 4).
// ---------------------------------------------------------------------------
__global__ void __launch_bounds__(256) xproj_kernel(const float* __restrict__ x,
                                                    const float* __restrict__ Wx) {
    __shared__ float xs[64][17];
    __shared__ float ws[96][17];
    const int m0  = blockIdx.x * 64;
    const int ks0 = blockIdx.y * 512;
    const int tid = threadIdx.x;
    const int tm  = tid >> 4;   // 0..15 -> rows tm*4..+3
    const int tn  = tid & 15;   // 0..15 -> cols tn*6..+5

    float acc[4][6];
#pragma unroll
    for (int i = 0; i < 4; i++)
#pragma unroll
        for (int j = 0; j < 6; j++) acc[i][j] = 0.f;

    for (int kt = 0; kt < 512; kt += 16) {
        const int kb = ks0 + kt;
#pragma unroll
        for (int e = 0; e < 4; e++) {
            int idx = e * 256 + tid;
            int r = idx >> 4, c = idx & 15;
            xs[r][c] = x[(m0 + r) * 2048 + kb + c];
        }
#pragma unroll
        for (int e = 0; e < 6; e++) {
            int idx = e * 256 + tid;
            int r = idx >> 4, c = idx & 15;
            ws[r][c] = Wx[r * 2048 + kb + c];
        }
        __syncthreads();
#pragma unroll
        for (int kk = 0; kk < 16; kk++) {
            float ar[4], br[6];
#pragma unroll
            for (int i = 0; i < 4; i++) ar[i] = xs[tm * 4 + i][kk];
#pragma unroll
            for (int j = 0; j < 6; j++) br[j] = ws[tn * 6 + j][kk];
#pragma unroll
            for (int i = 0; i < 4; i++)
#pragma unroll
                for (int j = 0; j < 6; j++)
                    acc[i][j] = fmaf(ar[i], br[j], acc[i][j]);
        }
        __syncthreads();
    }
    float* dst = g_xdbl_part + blockIdx.y * (MM * EE);
#pragma unroll
    for (int i = 0; i < 4; i++)
#pragma unroll
        for (int j = 0; j < 6; j++)
            dst[(m0 + tm * 4 + i) * EE + tn * 6 + j] = acc[i][j];
}

// Sum the 4 split-K partials.
__global__ void __launch_bounds__(256) reduce_xdbl() {
    const int n = MM * EE;
    int i = blockIdx.x * 256 + threadIdx.x;
    if (i < n)
        g_xdbl[i] = (g_xdbl_part[i] + g_xdbl_part[n + i])
                  + (g_xdbl_part[2 * n + i] + g_xdbl_part[3 * n + i]);
}

// ---------------------------------------------------------------------------
// Kernel 2: delta = softplus(dlt @ W_dt^T + b_dt)  (M=4096, N=2048, K=64)
// ---------------------------------------------------------------------------
__global__ void __launch_bounds__(256) delta_kernel(const float* __restrict__ Wdt,
                                                    const float* __restrict__ bdt) {
    __shared__ float as_[64][65];
    __shared__ float bs_[64][65];
    const int n0  = blockIdx.x * 64;
    const int m0  = blockIdx.y * 64;
    const int tid = threadIdx.x;

#pragma unroll
    for (int e = 0; e < 16; e++) {
        int idx = e * 256 + tid;
        int r = idx >> 6, c = idx & 63;
        as_[r][c] = g_xdbl[(m0 + r) * EE + c];
        bs_[r][c] = Wdt[(n0 + r) * 64 + c];
    }
    __syncthreads();

    const int tm = tid >> 4, tn = tid & 15;
    float acc[4][4] = {};
#pragma unroll 8
    for (int k = 0; k < 64; k++) {
        float ar[4], br[4];
#pragma unroll
        for (int i = 0; i < 4; i++) ar[i] = as_[tm * 4 + i][k];
#pragma unroll
        for (int j = 0; j < 4; j++) br[j] = bs_[tn * 4 + j][k];
#pragma unroll
        for (int i = 0; i < 4; i++)
#pragma unroll
            for (int j = 0; j < 4; j++)
                acc[i][j] = fmaf(ar[i], br[j], acc[i][j]);
    }

    const int n = n0 + tn * 4;
    float b0 = bdt[n + 0], b1 = bdt[n + 1], b2 = bdt[n + 2], b3 = bdt[n + 3];
#pragma unroll
    for (int i = 0; i < 4; i++) {
        int m = m0 + tm * 4 + i;
        float4 o;
        o.x = softplus_f(acc[i][0] + b0);
        o.y = softplus_f(acc[i][1] + b1);
        o.z = softplus_f(acc[i][2] + b2);
        o.w = softplus_f(acc[i][3] + b3);
        *(float4*)&g_delta[m * DD + n] = o;
    }
}

// ---------------------------------------------------------------------------
// Scan pass 1: per (channel, chunk) compute P = prod(exp(delta*A)) and
// q = local state (h starting from 0). Chunks 0..CHUNKS-2 only.
// Lane layout: lane = c*4 + s; 8 channels/warp, 4 state-quads/lane.
// grid (NCH/64, CHUNKS-1) x 256.
// ---------------------------------------------------------------------------
__global__ void __launch_bounds__(256) scan_pass1(const float* __restrict__ x,
                                                  const float* __restrict__ A_log) {
    const int tid  = threadIdx.x;
    const int warp = tid >> 5;
    const int lane = tid & 31;
    const int c    = lane >> 2;
    const int s    = lane & 3;
    const int chunk = blockIdx.y;
    const int ch   = blockIdx.x * 64 + warp * 8 + c;
    const int b    = ch >> 11;
    const int d    = ch & 2047;

    const float LOG2E = 1.4426950408889634f;
    float aa[4];
#pragma unroll
    for (int j = 0; j < 4; j++)
        aa[j] = -__expf(A_log[(d << 4) + (s << 2) + j]) * LOG2E;

    float P0 = 1.f, P1 = 1.f, P2 = 1.f, P3 = 1.f;
    float h0 = 0.f, h1 = 0.f, h2 = 0.f, h3 = 0.f;

    const int l0   = chunk * TT;
    const int base = (b * LL + l0) * DD + d;
    const float* pd = g_delta + base;
    const float* px = x + base;
    const float* pb = g_xdbl + (b * LL + l0) * EE + 64 + s * 4;

    float  dv = pd[0];
    float  uv = px[0];
    float4 Bv = *(const float4*)pb;

#pragma unroll 2
    for (int t = 0; t < TT; t++) {
        float  dvc = dv, uvc = uv;
        float4 Bc = Bv;
        if (t < TT - 1) {
            pd += DD; px += DD; pb += EE;
            dv = pd[0]; uv = px[0];
            Bv = *(const float4*)pb;
        }
        float a0 = ex2f(dvc * aa[0]);
        float a1 = ex2f(dvc * aa[1]);
        float a2 = ex2f(dvc * aa[2]);
        float a3 = ex2f(dvc * aa[3]);
        float du = dvc * uvc;
        h0 = fmaf(a0, h0, du * Bc.x);
        h1 = fmaf(a1, h1, du * Bc.y);
        h2 = fmaf(a2, h2, du * Bc.z);
        h3 = fmaf(a3, h3, du * Bc.w);
        P0 *= a0; P1 *= a1; P2 *= a2; P3 *= a3;
    }
    const int o = (chunk * NCH + ch) * NS + 4 * s;
    *(float4*)&g_P[o] = make_float4(P0, P1, P2, P3);
    *(float4*)&g_q[o] = make_float4(h0, h1, h2, h3);
}

// ---------------------------------------------------------------------------
// Scan pass 2: prefix-combine chunk transitions -> incoming state per chunk.
// ---------------------------------------------------------------------------
__global__ void __launch_bounds__(256) scan_pass2() {
    const int i = blockIdx.x * 256 + threadIdx.x;   // ch*16 + state, 65536 total
    float h = 0.f;
#pragma unroll
    for (int ck = 0; ck < CHUNKS; ck++) {
        g_hin[ck * (NCH * NS) + i] = h;
        if (ck < CHUNKS - 1)
            h = fmaf(g_P[ck * (NCH * NS) + i], h, g_q[ck * (NCH * NS) + i]);
    }
}

// ---------------------------------------------------------------------------
// Scan pass 3: full scan per chunk with correct incoming state; emit y.
// grid (NCH/64, CHUNKS) x 256.
// ---------------------------------------------------------------------------
__global__ void __launch_bounds__(256) scan_pass3(const float* __restrict__ x,
                                                  const float* __restrict__ A_log,
                                                  const float* __restrict__ Dp_,
                                                  float* __restrict__ out) {
    const int tid  = threadIdx.x;
    const int warp = tid >> 5;
    const int lane = tid & 31;
    const int c    = lane >> 2;
    const int s    = lane & 3;
    const int chunk = blockIdx.y;
    const int ch   = blockIdx.x * 64 + warp * 8 + c;
    const int b    = ch >> 11;
    const int d    = ch & 2047;

    const float LOG2E = 1.4426950408889634f;
    float aa[4];
#pragma unroll
    for (int j = 0; j < 4; j++)
        aa[j] = -__expf(A_log[(d << 4) + (s << 2) + j]) * LOG2E;
    const float Dv = Dp_[d];

    float4 h4 = *(const float4*)&g_hin[chunk * (NCH * NS) + ch * NS + 4 * s];
    float h0 = h4.x, h1 = h4.y, h2 = h4.z, h3 = h4.w;

    const int l0   = chunk * TT;
    const int base = (b * LL + l0) * DD + d;
    const float* pd = g_delta + base;
    const float* px = x + base;
    const float* pb = g_xdbl + (b * LL + l0) * EE + 64 + s * 4;
    float* po = out + base;

    float  dv = pd[0];
    float  uv = px[0];
    float4 Bv = *(const float4*)pb;
    float4 Cv = *(const float4*)(pb + 16);

#pragma unroll 2
    for (int t = 0; t < TT; t++) {
        float  dvc = dv, uvc = uv;
        float4 Bc = Bv, Cc = Cv;
        if (t < TT - 1) {
            pd += DD; px += DD; pb += EE;
            dv = pd[0]; uv = px[0];
            Bv = *(const float4*)pb;
            Cv = *(const float4*)(pb + 16);
        }
        float a0 = ex2f(dvc * aa[0]);
        float a1 = ex2f(dvc * aa[1]);
        float a2 = ex2f(dvc * aa[2]);
        float a3 = ex2f(dvc * aa[3]);
        float du = dvc * uvc;
        h0 = fmaf(a0, h0, du * Bc.x);
        h1 = fmaf(a1, h1, du * Bc.y);
        h2 = fmaf(a2, h2, du * Bc.z);
        h3 = fmaf(a3, h3, du * Bc.w);

        float y = h0 * Cc.x;
        y = fmaf(h1, Cc.y, y);
        y = fmaf(h2, Cc.z, y);
        y = fmaf(h3, Cc.w, y);
        y += __shfl_xor_sync(0xffffffffu, y, 1);
        y += __shfl_xor_sync(0xffffffffu, y, 2);

        if (s == 0) po[0] = fmaf(uvc, Dv, y);
        po += DD;
    }
}

// ---------------------------------------------------------------------------
extern "C" void kernel_launch(void* const* d_in, const int* in_sizes, int n_in,
                              void* d_out, int out_size) {
    const float* x     = (const float*)d_in[0];
    const float* Wx    = (const float*)d_in[1];
    const float* Wdt   = (const float*)d_in[2];
    const float* bdt   = (const float*)d_in[3];
    const float* A_log = (const float*)d_in[4];
    const float* Dp    = (const float*)d_in[5];
    float* out = (float*)d_out;

    xproj_kernel<<<dim3(MM / 64, KSPLIT), 256>>>(x, Wx);
    reduce_xdbl<<<(MM * EE + 255) / 256, 256>>>();
    delta_kernel<<<dim3(DD / 64, MM / 64), 256>>>(Wdt, bdt);
    scan_pass1<<<dim3(NCH / 64, CHUNKS - 1), 256>>>(x, A_log);
    scan_pass2<<<(NCH * NS) / 256, 256>>>();
    scan_pass3<<<dim3(NCH / 64, CHUNKS), 256>>>(x, A_log, Dp, out);
}